// round 3
// baseline (speedup 1.0000x reference)
#include <cuda_runtime.h>
#include <math.h>

// Problem constants
#define BB    8
#define CC    128
#define HIN   62
#define HH    64
#define WW    64
#define GG    4
#define GCC   32
#define PP    9
#define NPOS  (BB*HH*WW)   // 32768

// Scratch (device globals; no allocation allowed)
__device__ float g_xt[NPOS*CC];      // x padded+transposed to NHWC [8,64,64,128]; reused as out NHWC
__device__ float g_y[NPOS*CC];       // conv1x1 output NHWC
__device__ float g_xproj[NPOS*CC];   // in_proj output NHWC
__device__ float g_dg[NPOS*CC];      // dw+LN+GELU output NHWC
__device__ float g_samp[NPOS*CC];    // sampled output NHWC (bqgc)
__device__ float g_off[NPOS*72];
__device__ float g_mask[NPOS*36];
__device__ float g_cwT[CC*CC];       // conv_w transposed to [ci][co]

// ---------------------------------------------------------------------------
// conv_w [co,ci] -> [ci,co]
__global__ void transpose_w_kernel(const float* __restrict__ w, float* __restrict__ wt) {
    int i = blockIdx.x * 128 + threadIdx.x;
    int co = i >> 7, ci = i & 127;
    wt[ci * CC + co] = w[i];
}

// ---------------------------------------------------------------------------
// x NCHW [8,128,62,62] -> g_xt NHWC [8,64,64,128] with the 1-pixel zero border
// (1x1 conv with padding=1 grows spatial to 64x64; border rows are zero input).
__global__ void pack_x_kernel(const float* __restrict__ x, float* __restrict__ xt) {
    __shared__ float t[32][33];
    const int b  = blockIdx.z >> 6;
    const int h  = blockIdx.z & 63;
    const int w0 = blockIdx.x * 32;
    const int c0 = blockIdx.y * 32;
    const int tx = threadIdx.x, ty = threadIdx.y;
    // read x[b, c0+ty, h-1, w0+tx-1] (coalesced in tx over w)
    const int hh = h - 1;
    const int ww = w0 + tx - 1;
    const int cc = c0 + ty;
    float v = 0.f;
    if (hh >= 0 && hh < HIN && ww >= 0 && ww < HIN)
        v = x[(((size_t)b * CC + cc) * HIN + hh) * HIN + ww];
    t[ty][tx] = v;
    __syncthreads();
    // write xt[((b*64+h)*64 + w0+ty)*128 + c0+tx] (coalesced in tx over c)
    xt[(((size_t)b * HH + h) * WW + (w0 + ty)) * CC + (c0 + tx)] = t[tx][ty];
}

// ---------------------------------------------------------------------------
// out NHWC [8,64,64,128] -> d_out NCHW [8,128,64,64]
__global__ void unpack_out_kernel(const float* __restrict__ yo, float* __restrict__ out) {
    __shared__ float t[32][33];
    const int b  = blockIdx.z >> 6;
    const int h  = blockIdx.z & 63;
    const int w0 = blockIdx.x * 32;
    const int c0 = blockIdx.y * 32;
    const int tx = threadIdx.x, ty = threadIdx.y;
    // t[wy][cx] = yo[pos(w0+wy)*128 + c0+cx]  (coalesced in tx over c)
    t[ty][tx] = yo[(((size_t)b * HH + h) * WW + (w0 + ty)) * CC + (c0 + tx)];
    __syncthreads();
    // out[b, c0+ty, h, w0+tx] = t[tx][ty]  (coalesced in tx over w)
    out[(((size_t)b * CC + (c0 + ty)) * HH + h) * WW + (w0 + tx)] = t[tx][ty];
}

// ---------------------------------------------------------------------------
// Generic M x 128 x 128 GEMM: C = A @ W + bias.  W layout: [k][n] row-major.
// Block: 128 threads (one output column each), TM rows per block.
#define TM 32
__global__ void gemm128_kernel(const float* __restrict__ A, const float* __restrict__ Wm,
                               const float* __restrict__ bias, float* __restrict__ Cout) {
    __shared__ float sA[TM][CC];
    const int tid = threadIdx.x;
    const int m0  = blockIdx.x * TM;
    #pragma unroll
    for (int r = 0; r < TM; r++) sA[r][tid] = A[(size_t)(m0 + r) * CC + tid];
    __syncthreads();
    const float bb = bias[tid];
    #pragma unroll
    for (int r0 = 0; r0 < TM; r0 += 8) {
        float acc[8];
        #pragma unroll
        for (int i = 0; i < 8; i++) acc[i] = 0.f;
        #pragma unroll 4
        for (int k = 0; k < CC; k += 4) {
            const float w0 = Wm[(k + 0) * CC + tid];
            const float w1 = Wm[(k + 1) * CC + tid];
            const float w2 = Wm[(k + 2) * CC + tid];
            const float w3 = Wm[(k + 3) * CC + tid];
            #pragma unroll
            for (int i = 0; i < 8; i++) {
                float4 a = *reinterpret_cast<const float4*>(&sA[r0 + i][k]);
                acc[i] = fmaf(a.x, w0, acc[i]);
                acc[i] = fmaf(a.y, w1, acc[i]);
                acc[i] = fmaf(a.z, w2, acc[i]);
                acc[i] = fmaf(a.w, w3, acc[i]);
            }
        }
        #pragma unroll
        for (int i = 0; i < 8; i++)
            Cout[(size_t)(m0 + r0 + i) * CC + tid] = acc[i] + bb;
    }
}

// ---------------------------------------------------------------------------
// Depthwise 3x3 (pad 1) on y NHWC + bias + LayerNorm(C) + exact GELU -> g_dg
__global__ void dw_ln_gelu_kernel(const float* __restrict__ y,
                                  const float* __restrict__ dww,
                                  const float* __restrict__ dwb,
                                  const float* __restrict__ lng,
                                  const float* __restrict__ lnb,
                                  float* __restrict__ out) {
    const int pos = blockIdx.x;
    const int b = pos >> 12;
    const int h = (pos >> 6) & 63;
    const int w = pos & 63;
    const int c = threadIdx.x;

    float acc = dwb[c];
    #pragma unroll
    for (int i = 0; i < 3; i++) {
        const int hh = h + i - 1;
        if ((unsigned)hh < (unsigned)HH) {
            #pragma unroll
            for (int j = 0; j < 3; j++) {
                const int ww = w + j - 1;
                if ((unsigned)ww < (unsigned)WW)
                    acc += y[(((size_t)b * HH + hh) * WW + ww) * CC + c] * dww[c * 9 + i * 3 + j];
            }
        }
    }

    // block reduce sum & sumsq over 128 threads
    __shared__ float red[8];
    float s = acc, s2 = acc * acc;
    #pragma unroll
    for (int o = 16; o > 0; o >>= 1) {
        s  += __shfl_xor_sync(0xFFFFFFFFu, s,  o);
        s2 += __shfl_xor_sync(0xFFFFFFFFu, s2, o);
    }
    const int wid = c >> 5;
    if ((c & 31) == 0) { red[wid] = s; red[4 + wid] = s2; }
    __syncthreads();
    const float sum  = red[0] + red[1] + red[2] + red[3];
    const float sum2 = red[4] + red[5] + red[6] + red[7];
    const float mean = sum * (1.f / CC);
    const float var  = sum2 * (1.f / CC) - mean * mean;
    const float rstd = rsqrtf(var + 1e-5f);

    float v = (acc - mean) * rstd * lng[c] + lnb[c];
    // exact GELU
    v = 0.5f * v * (1.f + erff(v * 0.70710678118654752440f));
    out[(size_t)pos * CC + c] = v;
}

// ---------------------------------------------------------------------------
// Fused offset (N=72) + mask (N=36, softmax over P within each group) GEMM.
__global__ void off_mask_kernel(const float* __restrict__ A,
                                const float* __restrict__ offw, const float* __restrict__ offb,
                                const float* __restrict__ maskw, const float* __restrict__ maskb,
                                float* __restrict__ offOut, float* __restrict__ maskOut) {
    __shared__ float sA[TM][CC];
    __shared__ float sOut[TM][108];
    const int tid = threadIdx.x;
    const int m0  = blockIdx.x * TM;
    #pragma unroll
    for (int r = 0; r < TM; r++) sA[r][tid] = A[(size_t)(m0 + r) * CC + tid];
    __syncthreads();

    if (tid < 108) {
        const bool isOff = tid < 72;
        const float* Wp  = isOff ? offw : maskw;
        const int stride = isOff ? 72 : 36;
        const int col    = isOff ? tid : tid - 72;
        const float bb   = isOff ? offb[tid] : maskb[tid - 72];
        #pragma unroll
        for (int r0 = 0; r0 < TM; r0 += 8) {
            float acc[8];
            #pragma unroll
            for (int i = 0; i < 8; i++) acc[i] = 0.f;
            for (int k = 0; k < CC; k += 4) {
                const float w0 = Wp[(k + 0) * stride + col];
                const float w1 = Wp[(k + 1) * stride + col];
                const float w2 = Wp[(k + 2) * stride + col];
                const float w3 = Wp[(k + 3) * stride + col];
                #pragma unroll
                for (int i = 0; i < 8; i++) {
                    float4 a = *reinterpret_cast<const float4*>(&sA[r0 + i][k]);
                    acc[i] = fmaf(a.x, w0, acc[i]);
                    acc[i] = fmaf(a.y, w1, acc[i]);
                    acc[i] = fmaf(a.z, w2, acc[i]);
                    acc[i] = fmaf(a.w, w3, acc[i]);
                }
            }
            #pragma unroll
            for (int i = 0; i < 8; i++) sOut[r0 + i][tid] = acc[i] + bb;
        }
    }
    __syncthreads();

    if (tid < 72) {
        for (int r = 0; r < TM; r++)
            offOut[(size_t)(m0 + r) * 72 + tid] = sOut[r][tid];
    } else if (tid < 108) {
        const int j = tid - 72;       // mask column 0..35
        const int g = j / 9;
        for (int r = 0; r < TM; r++) {
            float mx = -1e30f;
            #pragma unroll
            for (int p = 0; p < 9; p++) mx = fmaxf(mx, sOut[r][72 + g * 9 + p]);
            float se = 0.f;
            #pragma unroll
            for (int p = 0; p < 9; p++) se += expf(sOut[r][72 + g * 9 + p] - mx);
            maskOut[(size_t)(m0 + r) * 36 + j] = expf(sOut[r][tid] - mx) / se;
        }
    }
}

// ---------------------------------------------------------------------------
// DCNv3 bilinear sampler. One position per block; thread = (g, c) pair.
// Padded coords: ix = w + 1 + dx + off_x ; nonzero sample iff 1<=xi<=64 && 1<=yi<=64.
__global__ void sampler_kernel(const float* __restrict__ xproj,
                               const float* __restrict__ off,
                               const float* __restrict__ mask,
                               float* __restrict__ out) {
    const int pos = blockIdx.x;
    const int b = pos >> 12;
    const int h = (pos >> 6) & 63;
    const int w = pos & 63;
    const int tid = threadIdx.x;
    const int g = tid >> 5;
    const int c = tid & 31;

    __shared__ float sOff[72];
    __shared__ float sM[36];
    if (tid < 72) sOff[tid] = off[(size_t)pos * 72 + tid];
    if (tid < 36) sM[tid]   = mask[(size_t)pos * 36 + tid];
    __syncthreads();

    const float* base = xproj + (size_t)b * (HH * WW * CC) + g * GCC + c;
    float acc = 0.f;
    #pragma unroll
    for (int p = 0; p < PP; p++) {
        const int gp = g * 9 + p;
        const float fix = (float)(w + p / 3) + sOff[2 * gp];      // = w+1+(p/3-1)+off_x
        const float fiy = (float)(h + p % 3) + sOff[2 * gp + 1];  // = h+1+(p%3-1)+off_y
        const float x0f = floorf(fix), y0f = floorf(fiy);
        const float fx = fix - x0f, fy = fiy - y0f;
        const int x0 = (int)x0f, y0 = (int)y0f;
        const float m = sM[gp];

        float v00 = 0.f, v10 = 0.f, v01 = 0.f, v11 = 0.f;
        const bool xv0 = (x0 >= 1) && (x0 <= 64);
        const bool xv1 = (x0 >= 0) && (x0 <= 63);
        const bool yv0 = (y0 >= 1) && (y0 <= 64);
        const bool yv1 = (y0 >= 0) && (y0 <= 63);
        if (yv0 && xv0) v00 = __ldg(base + ((size_t)(y0 - 1) * WW + (x0 - 1)) * CC);
        if (yv0 && xv1) v10 = __ldg(base + ((size_t)(y0 - 1) * WW + (x0    )) * CC);
        if (yv1 && xv0) v01 = __ldg(base + ((size_t)(y0    ) * WW + (x0 - 1)) * CC);
        if (yv1 && xv1) v11 = __ldg(base + ((size_t)(y0    ) * WW + (x0    )) * CC);

        acc += m * ((v00 * (1.f - fx) + v10 * fx) * (1.f - fy)
                  + (v01 * (1.f - fx) + v11 * fx) * fy);
    }
    out[(size_t)pos * CC + tid] = acc;
}

// ---------------------------------------------------------------------------
extern "C" void kernel_launch(void* const* d_in, const int* in_sizes, int n_in,
                              void* d_out, int out_size) {
    const float* x         = (const float*)d_in[0];
    const float* conv_w    = (const float*)d_in[1];
    const float* conv_b    = (const float*)d_in[2];
    const float* in_proj_w = (const float*)d_in[3];
    const float* in_proj_b = (const float*)d_in[4];
    const float* dw_w      = (const float*)d_in[5];
    const float* dw_b      = (const float*)d_in[6];
    const float* ln_g      = (const float*)d_in[7];
    const float* ln_b      = (const float*)d_in[8];
    const float* off_w     = (const float*)d_in[9];
    const float* off_b     = (const float*)d_in[10];
    const float* mask_w    = (const float*)d_in[11];
    const float* mask_b    = (const float*)d_in[12];
    const float* out_w     = (const float*)d_in[13];
    const float* out_b     = (const float*)d_in[14];
    float* out = (float*)d_out;

    float *xt, *y, *xproj, *dg, *samp, *offp, *maskp, *cwT;
    cudaGetSymbolAddress((void**)&xt,    g_xt);
    cudaGetSymbolAddress((void**)&y,     g_y);
    cudaGetSymbolAddress((void**)&xproj, g_xproj);
    cudaGetSymbolAddress((void**)&dg,    g_dg);
    cudaGetSymbolAddress((void**)&samp,  g_samp);
    cudaGetSymbolAddress((void**)&offp,  g_off);
    cudaGetSymbolAddress((void**)&maskp, g_mask);
    cudaGetSymbolAddress((void**)&cwT,   g_cwT);

    const dim3 tblk(32, 32);
    const dim3 tgrid(2, 4, BB * HH);

    // 1. transpose conv weight
    transpose_w_kernel<<<128, 128>>>(conv_w, cwT);
    // 2. pack x: NCHW -> NHWC with zero border (pad=1)
    pack_x_kernel<<<tgrid, tblk>>>(x, xt);
    // 3. 1x1 conv: y = xt @ conv_w^T + conv_b
    gemm128_kernel<<<NPOS / TM, CC>>>(xt, cwT, conv_b, y);
    // 4. in_proj: xproj = y @ in_proj_w + in_proj_b
    gemm128_kernel<<<NPOS / TM, CC>>>(y, in_proj_w, in_proj_b, xproj);
    // 5. depthwise 3x3 + LN + GELU
    dw_ln_gelu_kernel<<<NPOS, CC>>>(y, dw_w, dw_b, ln_g, ln_b, dg);
    // 6. offset + mask GEMM + softmax
    off_mask_kernel<<<NPOS / TM, CC>>>(dg, off_w, off_b, mask_w, mask_b, offp, maskp);
    // 7. deformable bilinear sampling
    sampler_kernel<<<NPOS, CC>>>(xproj, offp, maskp, samp);
    // 8. out_proj: reuse xt as NHWC output buffer
    gemm128_kernel<<<NPOS / TM, CC>>>(samp, out_w, out_b, xt);
    // 9. NHWC -> NCHW final output
    unpack_out_kernel<<<tgrid, tblk>>>(xt, out);
}

// round 6
// speedup vs baseline: 1.7455x; 1.7455x over previous
#include <cuda_runtime.h>
#include <math.h>
#include <cstdint>

// Problem constants
#define BB    8
#define CC    128
#define HIN   62
#define HH    64
#define WW    64
#define GG    4
#define GCC   32
#define PP    9
#define NPOS  (BB*HH*WW)   // 32768

// Scratch (device globals; no allocation allowed)
__device__ float g_xt[NPOS*CC];      // x padded+transposed NHWC; reused as out NHWC
__device__ float g_y[NPOS*CC];       // conv1x1 output NHWC
__device__ float g_xproj[NPOS*CC];   // in_proj output NHWC
__device__ float g_dg[NPOS*CC];      // dw+LN+GELU output NHWC
__device__ float g_samp[NPOS*CC];    // sampled output NHWC
__device__ float g_om[NPOS*CC];      // fused offset(72)+mask-logits(36)+pad output
__device__ float g_w1T[CC*CC];       // in_proj_w transposed  [n][k]
__device__ float g_w2P[CC*CC];       // fused off/mask weights [n][k], padded to 128
__device__ float g_w3T[CC*CC];       // out_proj_w transposed [n][k]
__device__ float g_b2[CC];           // fused off/mask bias, padded

// ===========================================================================
__device__ __forceinline__ uint32_t f2tf32(float f) {
    uint32_t r;
    asm("cvt.rna.tf32.f32 %0, %1;" : "=r"(r) : "f"(f));
    return r;
}
__device__ __forceinline__ void mma_tf32(float* c, const uint32_t* a, const uint32_t* b) {
    asm volatile(
        "mma.sync.aligned.m16n8k8.row.col.f32.tf32.tf32.f32 "
        "{%0,%1,%2,%3}, {%4,%5,%6,%7}, {%8,%9}, {%0,%1,%2,%3};"
        : "+f"(c[0]), "+f"(c[1]), "+f"(c[2]), "+f"(c[3])
        : "r"(a[0]), "r"(a[1]), "r"(a[2]), "r"(a[3]), "r"(b[0]), "r"(b[1]));
}

// ===========================================================================
// Weight prep: transposes + fused/padded offset-mask weight
// ===========================================================================
__global__ void prep_weights_kernel(const float* __restrict__ w1, const float* __restrict__ w3,
                                    const float* __restrict__ offw, const float* __restrict__ maskw,
                                    const float* __restrict__ offb, const float* __restrict__ maskb,
                                    float* __restrict__ w1T, float* __restrict__ w3T,
                                    float* __restrict__ w2P, float* __restrict__ b2) {
    const int n = blockIdx.x, k = threadIdx.x;
    w1T[n * CC + k] = w1[k * CC + n];
    w3T[n * CC + k] = w3[k * CC + n];
    float v = 0.f;
    if (n < 72)       v = offw[k * 72 + n];
    else if (n < 108) v = maskw[k * 36 + (n - 72)];
    w2P[n * CC + k] = v;
    if (k == 0) b2[n] = (n < 72) ? offb[n] : ((n < 108) ? maskb[n - 72] : 0.f);
}

// ===========================================================================
// x NCHW [8,128,62,62] -> NHWC [8,64,64,128] with 1-px zero border
// ===========================================================================
__global__ void pack_x_kernel(const float* __restrict__ x, float* __restrict__ xt) {
    __shared__ float t[32][33];
    const int b  = blockIdx.z >> 6;
    const int h  = blockIdx.z & 63;
    const int w0 = blockIdx.x * 32;
    const int c0 = blockIdx.y * 32;
    const int tx = threadIdx.x, ty = threadIdx.y;
    const int hh = h - 1;
    const int ww = w0 + tx - 1;
    const int cc = c0 + ty;
    float v = 0.f;
    if (hh >= 0 && hh < HIN && ww >= 0 && ww < HIN)
        v = x[(((size_t)b * CC + cc) * HIN + hh) * HIN + ww];
    t[ty][tx] = v;
    __syncthreads();
    xt[(((size_t)b * HH + h) * WW + (w0 + ty)) * CC + (c0 + tx)] = t[tx][ty];
}

__global__ void unpack_out_kernel(const float* __restrict__ yo, float* __restrict__ out) {
    __shared__ float t[32][33];
    const int b  = blockIdx.z >> 6;
    const int h  = blockIdx.z & 63;
    const int w0 = blockIdx.x * 32;
    const int c0 = blockIdx.y * 32;
    const int tx = threadIdx.x, ty = threadIdx.y;
    t[ty][tx] = yo[(((size_t)b * HH + h) * WW + (w0 + ty)) * CC + (c0 + tx)];
    __syncthreads();
    out[(((size_t)b * CC + (c0 + ty)) * HH + h) * WW + (w0 + tx)] = t[tx][ty];
}

// ===========================================================================
// HMMA tf32 GEMM: C[M,128] = A[M,128] @ B^T + bias, B given [n][k] row-major.
// CTA = 256 threads = 8 warps (4 x 2). Warp tile = 32 rows x 64 cols.
// mma.m16n8k8 row.col: A row-major [m][k], B "col-major" == [n][k] layout.
// SMEM rows padded to 132 floats: frag LDS conflict-free (4*row+col distinct).
// ===========================================================================
#define SPITCH 132
#define GEMM_SMEM (2 * CC * SPITCH * 4)

__global__ void __launch_bounds__(256, 1)
hmma_gemm_kernel(const float* __restrict__ A, const float* __restrict__ Bm,
                 const float* __restrict__ bias, float* __restrict__ Cout) {
    extern __shared__ float smem[];
    float* sA = smem;                 // [128][132]
    float* sB = smem + CC * SPITCH;   // [128][132]

    const int tid  = threadIdx.x;
    const int lane = tid & 31;
    const int wid  = tid >> 5;
    const int gid  = lane >> 2;   // 0..7
    const int tg   = lane & 3;    // 0..3
    const int warp_m = wid & 3;   // 0..3  (32 rows each)
    const int warp_n = wid >> 2;  // 0..1  (64 cols each)
    const int m0 = blockIdx.x * 128;

    // Cooperative load + tf32 round-to-nearest into SMEM.
    // 128 rows x 32 float4 per tile; 256 threads -> 16 float4 each per tile.
    #pragma unroll
    for (int i = 0; i < 16; i++) {
        const int idx = i * 256 + tid;
        const int row = idx >> 5;
        const int c4  = idx & 31;
        float4 va = *reinterpret_cast<const float4*>(A + (size_t)(m0 + row) * CC + c4 * 4);
        float4 vb = *reinterpret_cast<const float4*>(Bm + (size_t)row * CC + c4 * 4);
        uint4 ta, tb;
        ta.x = f2tf32(va.x); ta.y = f2tf32(va.y); ta.z = f2tf32(va.z); ta.w = f2tf32(va.w);
        tb.x = f2tf32(vb.x); tb.y = f2tf32(vb.y); tb.z = f2tf32(vb.z); tb.w = f2tf32(vb.w);
        *reinterpret_cast<uint4*>(sA + row * SPITCH + c4 * 4) = ta;
        *reinterpret_cast<uint4*>(sB + row * SPITCH + c4 * 4) = tb;
    }
    __syncthreads();

    float acc[2][8][4];
    #pragma unroll
    for (int mi = 0; mi < 2; mi++)
        #pragma unroll
        for (int ni = 0; ni < 8; ni++)
            #pragma unroll
            for (int j = 0; j < 4; j++) acc[mi][ni][j] = 0.f;

    const uint32_t* uA = reinterpret_cast<const uint32_t*>(sA);
    const uint32_t* uB = reinterpret_cast<const uint32_t*>(sB);
    const int arow0 = warp_m * 32 + gid;        // + mi*16 (+8 inside frag)
    const int bcol0 = warp_n * 64 + gid;        // + ni*8

    for (int ks = 0; ks < 16; ks++) {
        const int k8 = ks * 8;
        uint32_t af[2][4];
        #pragma unroll
        for (int mi = 0; mi < 2; mi++) {
            const int r = arow0 + mi * 16;
            af[mi][0] = uA[(r    ) * SPITCH + k8 + tg];
            af[mi][1] = uA[(r + 8) * SPITCH + k8 + tg];
            af[mi][2] = uA[(r    ) * SPITCH + k8 + tg + 4];
            af[mi][3] = uA[(r + 8) * SPITCH + k8 + tg + 4];
        }
        #pragma unroll
        for (int ni = 0; ni < 8; ni++) {
            uint32_t bf[2];
            const int n = bcol0 + ni * 8;
            bf[0] = uB[n * SPITCH + k8 + tg];
            bf[1] = uB[n * SPITCH + k8 + tg + 4];
            mma_tf32(acc[0][ni], af[0], bf);
            mma_tf32(acc[1][ni], af[1], bf);
        }
    }

    // Epilogue: C rows = arow0 + mi*16 (+8), cols = warp_n*64 + ni*8 + 2*tg (+1)
    float2 bb[8];
    #pragma unroll
    for (int ni = 0; ni < 8; ni++) {
        const int col = warp_n * 64 + ni * 8 + 2 * tg;
        bb[ni].x = __ldg(bias + col);
        bb[ni].y = __ldg(bias + col + 1);
    }
    #pragma unroll
    for (int mi = 0; mi < 2; mi++) {
        const int r0 = m0 + arow0 + mi * 16;
        #pragma unroll
        for (int ni = 0; ni < 8; ni++) {
            const int col = warp_n * 64 + ni * 8 + 2 * tg;
            float2 v0 = make_float2(acc[mi][ni][0] + bb[ni].x, acc[mi][ni][1] + bb[ni].y);
            float2 v1 = make_float2(acc[mi][ni][2] + bb[ni].x, acc[mi][ni][3] + bb[ni].y);
            *reinterpret_cast<float2*>(Cout + (size_t)r0 * CC + col)       = v0;
            *reinterpret_cast<float2*>(Cout + (size_t)(r0 + 8) * CC + col) = v1;
        }
    }
}

// ===========================================================================
// Depthwise 3x3 (pad 1) on y NHWC + bias + LayerNorm(C) + exact GELU
// ===========================================================================
__global__ void dw_ln_gelu_kernel(const float* __restrict__ y,
                                  const float* __restrict__ dww,
                                  const float* __restrict__ dwb,
                                  const float* __restrict__ lng,
                                  const float* __restrict__ lnb,
                                  float* __restrict__ out) {
    const int pos = blockIdx.x;
    const int b = pos >> 12;
    const int h = (pos >> 6) & 63;
    const int w = pos & 63;
    const int c = threadIdx.x;

    float acc = dwb[c];
    #pragma unroll
    for (int i = 0; i < 3; i++) {
        const int hh = h + i - 1;
        if ((unsigned)hh < (unsigned)HH) {
            #pragma unroll
            for (int j = 0; j < 3; j++) {
                const int ww = w + j - 1;
                if ((unsigned)ww < (unsigned)WW)
                    acc += y[(((size_t)b * HH + hh) * WW + ww) * CC + c] * dww[c * 9 + i * 3 + j];
            }
        }
    }

    __shared__ float red[8];
    float s = acc, s2 = acc * acc;
    #pragma unroll
    for (int o = 16; o > 0; o >>= 1) {
        s  += __shfl_xor_sync(0xFFFFFFFFu, s,  o);
        s2 += __shfl_xor_sync(0xFFFFFFFFu, s2, o);
    }
    const int wid = c >> 5;
    if ((c & 31) == 0) { red[wid] = s; red[4 + wid] = s2; }
    __syncthreads();
    const float sum  = red[0] + red[1] + red[2] + red[3];
    const float sum2 = red[4] + red[5] + red[6] + red[7];
    const float mean = sum * (1.f / CC);
    const float var  = sum2 * (1.f / CC) - mean * mean;
    const float rstd = rsqrtf(var + 1e-5f);

    float v = (acc - mean) * rstd * lng[c] + lnb[c];
    v = 0.5f * v * (1.f + erff(v * 0.70710678118654752440f));
    out[(size_t)pos * CC + c] = v;
}

// ===========================================================================
// DCNv3 bilinear sampler with fused group softmax over mask logits.
// om layout per position: [0:72) offsets, [72:108) mask logits, [108:128) pad.
// ===========================================================================
__global__ void sampler_kernel(const float* __restrict__ xproj,
                               const float* __restrict__ om,
                               float* __restrict__ out) {
    const int pos = blockIdx.x;
    const int b = pos >> 12;
    const int h = (pos >> 6) & 63;
    const int w = pos & 63;
    const int tid = threadIdx.x;
    const int g = tid >> 5;
    const int c = tid & 31;

    __shared__ float sRaw[108];
    __shared__ float sM[36];
    if (tid < 108) sRaw[tid] = om[(size_t)pos * CC + tid];
    __syncthreads();
    if (tid >= 72 && tid < 108) {
        const int j = tid - 72;
        const int gg = j / 9;
        float mx = -1e30f;
        #pragma unroll
        for (int p = 0; p < 9; p++) mx = fmaxf(mx, sRaw[72 + gg * 9 + p]);
        float se = 0.f;
        #pragma unroll
        for (int p = 0; p < 9; p++) se += expf(sRaw[72 + gg * 9 + p] - mx);
        sM[j] = expf(sRaw[tid] - mx) / se;
    }
    __syncthreads();

    const float* base = xproj + (size_t)b * (HH * WW * CC) + g * GCC + c;
    float acc = 0.f;
    #pragma unroll
    for (int p = 0; p < PP; p++) {
        const int gp = g * 9 + p;
        const float fix = (float)(w + p / 3) + sRaw[2 * gp];
        const float fiy = (float)(h + p % 3) + sRaw[2 * gp + 1];
        const float x0f = floorf(fix), y0f = floorf(fiy);
        const float fx = fix - x0f, fy = fiy - y0f;
        const int x0 = (int)x0f, y0 = (int)y0f;
        const float m = sM[gp];

        float v00 = 0.f, v10 = 0.f, v01 = 0.f, v11 = 0.f;
        const bool xv0 = (x0 >= 1) && (x0 <= 64);
        const bool xv1 = (x0 >= 0) && (x0 <= 63);
        const bool yv0 = (y0 >= 1) && (y0 <= 64);
        const bool yv1 = (y0 >= 0) && (y0 <= 63);
        if (yv0 && xv0) v00 = __ldg(base + ((size_t)(y0 - 1) * WW + (x0 - 1)) * CC);
        if (yv0 && xv1) v10 = __ldg(base + ((size_t)(y0 - 1) * WW + (x0    )) * CC);
        if (yv1 && xv0) v01 = __ldg(base + ((size_t)(y0    ) * WW + (x0 - 1)) * CC);
        if (yv1 && xv1) v11 = __ldg(base + ((size_t)(y0    ) * WW + (x0    )) * CC);

        acc += m * ((v00 * (1.f - fx) + v10 * fx) * (1.f - fy)
                  + (v01 * (1.f - fx) + v11 * fx) * fy);
    }
    out[(size_t)pos * CC + tid] = acc;
}

// ===========================================================================
extern "C" void kernel_launch(void* const* d_in, const int* in_sizes, int n_in,
                              void* d_out, int out_size) {
    const float* x         = (const float*)d_in[0];
    const float* conv_w    = (const float*)d_in[1];
    const float* conv_b    = (const float*)d_in[2];
    const float* in_proj_w = (const float*)d_in[3];
    const float* in_proj_b = (const float*)d_in[4];
    const float* dw_w      = (const float*)d_in[5];
    const float* dw_b      = (const float*)d_in[6];
    const float* ln_g      = (const float*)d_in[7];
    const float* ln_b      = (const float*)d_in[8];
    const float* off_w     = (const float*)d_in[9];
    const float* off_b     = (const float*)d_in[10];
    const float* mask_w    = (const float*)d_in[11];
    const float* mask_b    = (const float*)d_in[12];
    const float* out_w     = (const float*)d_in[13];
    const float* out_b     = (const float*)d_in[14];
    float* out = (float*)d_out;

    float *xt, *y, *xproj, *dg, *samp, *omp, *w1T, *w2P, *w3T, *b2;
    cudaGetSymbolAddress((void**)&xt,    g_xt);
    cudaGetSymbolAddress((void**)&y,     g_y);
    cudaGetSymbolAddress((void**)&xproj, g_xproj);
    cudaGetSymbolAddress((void**)&dg,    g_dg);
    cudaGetSymbolAddress((void**)&samp,  g_samp);
    cudaGetSymbolAddress((void**)&omp,   g_om);
    cudaGetSymbolAddress((void**)&w1T,   g_w1T);
    cudaGetSymbolAddress((void**)&w2P,   g_w2P);
    cudaGetSymbolAddress((void**)&w3T,   g_w3T);
    cudaGetSymbolAddress((void**)&b2,    g_b2);

    static bool attr_done = false;
    if (!attr_done) {
        cudaFuncSetAttribute(hmma_gemm_kernel,
                             cudaFuncAttributeMaxDynamicSharedMemorySize, GEMM_SMEM);
        attr_done = true;
    }

    const dim3 tblk(32, 32);
    const dim3 tgrid(2, 4, BB * HH);

    // 1. weight prep (transposes + fused padded off/mask weight)
    prep_weights_kernel<<<CC, CC>>>(in_proj_w, out_w, off_w, mask_w, off_b, mask_b,
                                    w1T, w3T, w2P, b2);
    // 2. pack x: NCHW -> NHWC with zero border (pad=1)
    pack_x_kernel<<<tgrid, tblk>>>(x, xt);
    // 3. 1x1 conv: y = xt @ conv_w^T + conv_b  (conv_w already [n][k])
    hmma_gemm_kernel<<<NPOS / 128, 256, GEMM_SMEM>>>(xt, conv_w, conv_b, y);
    // 4. in_proj
    hmma_gemm_kernel<<<NPOS / 128, 256, GEMM_SMEM>>>(y, w1T, in_proj_b, xproj);
    // 5. depthwise 3x3 + LN + GELU
    dw_ln_gelu_kernel<<<NPOS, CC>>>(y, dw_w, dw_b, ln_g, ln_b, dg);
    // 6. fused offset+mask GEMM (softmax deferred into sampler)
    hmma_gemm_kernel<<<NPOS / 128, 256, GEMM_SMEM>>>(dg, w2P, b2, omp);
    // 7. deformable bilinear sampling (+ inline group softmax)
    sampler_kernel<<<NPOS, CC>>>(xproj, omp, samp);
    // 8. out_proj (reuse xt as NHWC output buffer)
    hmma_gemm_kernel<<<NPOS / 128, 256, GEMM_SMEM>>>(samp, w3T, out_b, xt);
    // 9. NHWC -> NCHW final output
    unpack_out_kernel<<<tgrid, tblk>>>(xt, out);
}

// round 7
// speedup vs baseline: 2.3842x; 1.3660x over previous
#include <cuda_runtime.h>
#include <math.h>
#include <cstdint>

// Problem constants
#define BB    8
#define CC    128
#define HIN   62
#define HH    64
#define WW    64
#define GG    4
#define GCC   32
#define PP    9
#define NPOS  (BB*HH*WW)   // 32768

// Scratch (device globals; no allocation allowed)
__device__ float g_xt[NPOS*CC];      // x padded+transposed NHWC; reused as out NHWC
__device__ float g_y[NPOS*CC];       // conv1x1 output NHWC
__device__ float g_xproj[NPOS*CC];   // in_proj output NHWC
__device__ float g_dg[NPOS*CC];      // dw+LN+GELU output NHWC
__device__ float g_samp[NPOS*CC];    // sampled output NHWC
__device__ float g_om[NPOS*CC];      // fused offset(72)+mask-logits(36)+pad
__device__ float g_w1T[CC*CC];       // in_proj_w transposed  [n][k]
__device__ float g_w2P[CC*CC];       // fused off/mask weights [n][k], padded
__device__ float g_w3T[CC*CC];       // out_proj_w transposed [n][k]
__device__ float g_b2[CC];           // fused off/mask bias, padded

// ===========================================================================
__device__ __forceinline__ uint32_t f2tf32(float f) {
    uint32_t r;
    asm("cvt.rna.tf32.f32 %0, %1;" : "=r"(r) : "f"(f));
    return r;
}
__device__ __forceinline__ void mma_tf32(float* c, const uint32_t* a, const uint32_t* b) {
    asm volatile(
        "mma.sync.aligned.m16n8k8.row.col.f32.tf32.tf32.f32 "
        "{%0,%1,%2,%3}, {%4,%5,%6,%7}, {%8,%9}, {%0,%1,%2,%3};"
        : "+f"(c[0]), "+f"(c[1]), "+f"(c[2]), "+f"(c[3])
        : "r"(a[0]), "r"(a[1]), "r"(a[2]), "r"(a[3]), "r"(b[0]), "r"(b[1]));
}

// ===========================================================================
// Weight prep: transposes + fused/padded offset-mask weight
// ===========================================================================
__global__ void prep_weights_kernel(const float* __restrict__ w1, const float* __restrict__ w3,
                                    const float* __restrict__ offw, const float* __restrict__ maskw,
                                    const float* __restrict__ offb, const float* __restrict__ maskb,
                                    float* __restrict__ w1T, float* __restrict__ w3T,
                                    float* __restrict__ w2P, float* __restrict__ b2) {
    const int n = blockIdx.x, k = threadIdx.x;
    w1T[n * CC + k] = w1[k * CC + n];
    w3T[n * CC + k] = w3[k * CC + n];
    float v = 0.f;
    if (n < 72)       v = offw[k * 72 + n];
    else if (n < 108) v = maskw[k * 36 + (n - 72)];
    w2P[n * CC + k] = v;
    if (k == 0) b2[n] = (n < 72) ? offb[n] : ((n < 108) ? maskb[n - 72] : 0.f);
}

// ===========================================================================
// x NCHW [8,128,62,62] -> NHWC [8,64,64,128] with 1-px zero border
// ===========================================================================
__global__ void pack_x_kernel(const float* __restrict__ x, float* __restrict__ xt) {
    __shared__ float t[32][33];
    const int b  = blockIdx.z >> 6;
    const int h  = blockIdx.z & 63;
    const int w0 = blockIdx.x * 32;
    const int c0 = blockIdx.y * 32;
    const int tx = threadIdx.x, ty = threadIdx.y;
    const int hh = h - 1;
    const int ww = w0 + tx - 1;
    const int cc = c0 + ty;
    float v = 0.f;
    if (hh >= 0 && hh < HIN && ww >= 0 && ww < HIN)
        v = x[(((size_t)b * CC + cc) * HIN + hh) * HIN + ww];
    t[ty][tx] = v;
    __syncthreads();
    xt[(((size_t)b * HH + h) * WW + (w0 + ty)) * CC + (c0 + tx)] = t[tx][ty];
}

__global__ void unpack_out_kernel(const float* __restrict__ yo, float* __restrict__ out) {
    __shared__ float t[32][33];
    const int b  = blockIdx.z >> 6;
    const int h  = blockIdx.z & 63;
    const int w0 = blockIdx.x * 32;
    const int c0 = blockIdx.y * 32;
    const int tx = threadIdx.x, ty = threadIdx.y;
    t[ty][tx] = yo[(((size_t)b * HH + h) * WW + (w0 + ty)) * CC + (c0 + tx)];
    __syncthreads();
    out[(((size_t)b * CC + (c0 + ty)) * HH + h) * WW + (w0 + tx)] = t[tx][ty];
}

// ===========================================================================
// HMMA tf32 GEMM, split-N: C[M,128] = A[M,128] @ B^T + bias, B given [n][k].
// CTA = 256 threads = 8 warps (4m x 2n). CTA tile = 128 rows x 64 cols.
// smem = A[128][132] + B[64][132] = 101.4KB -> 2 CTAs/SM.
// ===========================================================================
#define SPITCH 132
#define GEMM_SMEM ((CC * SPITCH + 64 * SPITCH) * 4)

__global__ void __launch_bounds__(256, 2)
hmma_gemm_kernel(const float* __restrict__ A, const float* __restrict__ Bm,
                 const float* __restrict__ bias, float* __restrict__ Cout) {
    extern __shared__ float smem[];
    float* sA = smem;                 // [128][132]
    float* sB = smem + CC * SPITCH;   // [64][132]

    const int tid  = threadIdx.x;
    const int lane = tid & 31;
    const int wid  = tid >> 5;
    const int gid  = lane >> 2;   // 0..7
    const int tg   = lane & 3;    // 0..3
    const int warp_m = wid & 3;   // 0..3  (32 rows each)
    const int warp_n = wid >> 2;  // 0..1  (32 cols each)
    const int m0 = blockIdx.x * 128;
    const int n0 = blockIdx.y * 64;

    // A: 128 rows x 32 float4 = 4096 float4; 16 per thread.
    #pragma unroll
    for (int i = 0; i < 16; i++) {
        const int idx = i * 256 + tid;
        const int row = idx >> 5;
        const int c4  = idx & 31;
        float4 va = *reinterpret_cast<const float4*>(A + (size_t)(m0 + row) * CC + c4 * 4);
        uint4 ta;
        ta.x = f2tf32(va.x); ta.y = f2tf32(va.y); ta.z = f2tf32(va.z); ta.w = f2tf32(va.w);
        *reinterpret_cast<uint4*>(sA + row * SPITCH + c4 * 4) = ta;
    }
    // B: 64 rows x 32 float4 = 2048 float4; 8 per thread.
    #pragma unroll
    for (int i = 0; i < 8; i++) {
        const int idx = i * 256 + tid;
        const int row = idx >> 5;
        const int c4  = idx & 31;
        float4 vb = *reinterpret_cast<const float4*>(Bm + (size_t)(n0 + row) * CC + c4 * 4);
        uint4 tb;
        tb.x = f2tf32(vb.x); tb.y = f2tf32(vb.y); tb.z = f2tf32(vb.z); tb.w = f2tf32(vb.w);
        *reinterpret_cast<uint4*>(sB + row * SPITCH + c4 * 4) = tb;
    }
    __syncthreads();

    float acc[2][4][4];
    #pragma unroll
    for (int mi = 0; mi < 2; mi++)
        #pragma unroll
        for (int ni = 0; ni < 4; ni++)
            #pragma unroll
            for (int j = 0; j < 4; j++) acc[mi][ni][j] = 0.f;

    const uint32_t* uA = reinterpret_cast<const uint32_t*>(sA);
    const uint32_t* uB = reinterpret_cast<const uint32_t*>(sB);
    const int arow0 = warp_m * 32 + gid;
    const int bcol0 = warp_n * 32 + gid;

    #pragma unroll 4
    for (int ks = 0; ks < 16; ks++) {
        const int k8 = ks * 8;
        uint32_t af[2][4];
        #pragma unroll
        for (int mi = 0; mi < 2; mi++) {
            const int r = arow0 + mi * 16;
            af[mi][0] = uA[(r    ) * SPITCH + k8 + tg];
            af[mi][1] = uA[(r + 8) * SPITCH + k8 + tg];
            af[mi][2] = uA[(r    ) * SPITCH + k8 + tg + 4];
            af[mi][3] = uA[(r + 8) * SPITCH + k8 + tg + 4];
        }
        #pragma unroll
        for (int ni = 0; ni < 4; ni++) {
            uint32_t bf[2];
            const int n = bcol0 + ni * 8;
            bf[0] = uB[n * SPITCH + k8 + tg];
            bf[1] = uB[n * SPITCH + k8 + tg + 4];
            mma_tf32(acc[0][ni], af[0], bf);
            mma_tf32(acc[1][ni], af[1], bf);
        }
    }

    float2 bb[4];
    #pragma unroll
    for (int ni = 0; ni < 4; ni++) {
        const int col = n0 + warp_n * 32 + ni * 8 + 2 * tg;
        bb[ni].x = __ldg(bias + col);
        bb[ni].y = __ldg(bias + col + 1);
    }
    #pragma unroll
    for (int mi = 0; mi < 2; mi++) {
        const int r0 = m0 + arow0 + mi * 16;
        #pragma unroll
        for (int ni = 0; ni < 4; ni++) {
            const int col = n0 + warp_n * 32 + ni * 8 + 2 * tg;
            float2 v0 = make_float2(acc[mi][ni][0] + bb[ni].x, acc[mi][ni][1] + bb[ni].y);
            float2 v1 = make_float2(acc[mi][ni][2] + bb[ni].x, acc[mi][ni][3] + bb[ni].y);
            *reinterpret_cast<float2*>(Cout + (size_t)r0 * CC + col)       = v0;
            *reinterpret_cast<float2*>(Cout + (size_t)(r0 + 8) * CC + col) = v1;
        }
    }
}

// ===========================================================================
// Depthwise 3x3 (pad 1) + bias + LayerNorm(C) + exact GELU.
// Block = 256 threads = 8 warps; warp = one position, lane = 4 channels.
// ===========================================================================
__global__ void __launch_bounds__(256)
dw_ln_gelu_kernel(const float* __restrict__ y,
                  const float* __restrict__ dww,
                  const float* __restrict__ dwb,
                  const float* __restrict__ lng,
                  const float* __restrict__ lnb,
                  float* __restrict__ out) {
    __shared__ float sW[9 * CC];   // transposed: [tap][c]
    const int tid = threadIdx.x;
    for (int i = tid; i < 9 * CC; i += 256) {
        const int c = i / 9, tap = i % 9;
        sW[tap * CC + c] = dww[i];
    }
    __syncthreads();

    const int wid  = tid >> 5;
    const int lane = tid & 31;
    const int pos  = blockIdx.x * 8 + wid;
    const int b = pos >> 12;
    const int h = (pos >> 6) & 63;
    const int w = pos & 63;
    const int c4 = lane * 4;

    const float4 bv = __ldg(reinterpret_cast<const float4*>(dwb + c4));
    float4 acc = bv;
    const float* ybase = y + (((size_t)b * HH + h) * WW + w) * CC + c4;
    #pragma unroll
    for (int i = 0; i < 3; i++) {
        const int hh = h + i - 1;
        if ((unsigned)hh >= (unsigned)HH) continue;
        #pragma unroll
        for (int j = 0; j < 3; j++) {
            const int ww = w + j - 1;
            if ((unsigned)ww >= (unsigned)WW) continue;
            const float4 v = __ldg(reinterpret_cast<const float4*>(
                ybase + ((i - 1) * WW + (j - 1)) * CC));
            const float4 wt = *reinterpret_cast<const float4*>(sW + (i * 3 + j) * CC + c4);
            acc.x = fmaf(v.x, wt.x, acc.x);
            acc.y = fmaf(v.y, wt.y, acc.y);
            acc.z = fmaf(v.z, wt.z, acc.z);
            acc.w = fmaf(v.w, wt.w, acc.w);
        }
    }

    // LayerNorm over 128 channels = warp-wide reduction (lane holds 4).
    float s  = acc.x + acc.y + acc.z + acc.w;
    float s2 = acc.x * acc.x + acc.y * acc.y + acc.z * acc.z + acc.w * acc.w;
    #pragma unroll
    for (int o = 16; o > 0; o >>= 1) {
        s  += __shfl_xor_sync(0xFFFFFFFFu, s,  o);
        s2 += __shfl_xor_sync(0xFFFFFFFFu, s2, o);
    }
    const float mean = s * (1.f / CC);
    const float var  = s2 * (1.f / CC) - mean * mean;
    const float rstd = rsqrtf(var + 1e-5f);

    const float4 gv = __ldg(reinterpret_cast<const float4*>(lng + c4));
    const float4 betav = __ldg(reinterpret_cast<const float4*>(lnb + c4));
    float4 o4;
    {
        float v0 = (acc.x - mean) * rstd * gv.x + betav.x;
        float v1 = (acc.y - mean) * rstd * gv.y + betav.y;
        float v2 = (acc.z - mean) * rstd * gv.z + betav.z;
        float v3 = (acc.w - mean) * rstd * gv.w + betav.w;
        const float k = 0.70710678118654752440f;
        o4.x = 0.5f * v0 * (1.f + erff(v0 * k));
        o4.y = 0.5f * v1 * (1.f + erff(v1 * k));
        o4.z = 0.5f * v2 * (1.f + erff(v2 * k));
        o4.w = 0.5f * v3 * (1.f + erff(v3 * k));
    }
    *reinterpret_cast<float4*>(out + (size_t)pos * CC + c4) = o4;
}

// ===========================================================================
// DCNv3 bilinear sampler + fused group softmax. Block = 128 threads = 4 warps;
// warp = one position; lane: g = lane>>3, channels = g*32 + (lane&7)*4.
// ===========================================================================
__global__ void __launch_bounds__(128)
sampler_kernel(const float* __restrict__ xproj,
               const float* __restrict__ om,
               float* __restrict__ out) {
    __shared__ float sOM[4][112];
    const int tid  = threadIdx.x;
    const int wid  = tid >> 5;
    const int lane = tid & 31;
    const int pos  = blockIdx.x * 4 + wid;
    const int b = pos >> 12;
    const int h = (pos >> 6) & 63;
    const int w = pos & 63;
    const int g  = lane >> 3;
    const int c4 = (lane & 7) * 4;

    // warp loads its own om row (108 floats)
    #pragma unroll
    for (int r = 0; r < 4; r++) {
        const int i = r * 32 + lane;
        if (i < 108) sOM[wid][i] = __ldg(om + (size_t)pos * CC + i);
    }
    __syncwarp();

    // group softmax (each lane computes its own group's normalizer)
    const float* logit = &sOM[wid][72 + g * 9];
    float mx = -1e30f;
    #pragma unroll
    for (int p = 0; p < 9; p++) mx = fmaxf(mx, logit[p]);
    float se = 0.f;
    float ex[9];
    #pragma unroll
    for (int p = 0; p < 9; p++) { ex[p] = expf(logit[p] - mx); se += ex[p]; }
    const float inv_se = 1.f / se;

    const float* base = xproj + (size_t)b * (HH * WW * CC) + g * GCC + c4;
    float4 acc = make_float4(0.f, 0.f, 0.f, 0.f);
    #pragma unroll
    for (int p = 0; p < PP; p++) {
        const int gp = g * 9 + p;
        const float fix = (float)(w + p / 3) + sOM[wid][2 * gp];
        const float fiy = (float)(h + p % 3) + sOM[wid][2 * gp + 1];
        const float x0f = floorf(fix), y0f = floorf(fiy);
        const float fx = fix - x0f, fy = fiy - y0f;
        const int x0 = (int)x0f, y0 = (int)y0f;
        const float m = ex[p] * inv_se;

        const bool xv0 = (x0 >= 1) && (x0 <= 64);
        const bool xv1 = (x0 >= 0) && (x0 <= 63);
        const bool yv0 = (y0 >= 1) && (y0 <= 64);
        const bool yv1 = (y0 >= 0) && (y0 <= 63);
        float4 v00 = make_float4(0,0,0,0), v10 = v00, v01 = v00, v11 = v00;
        if (yv0 && xv0) v00 = __ldg(reinterpret_cast<const float4*>(base + ((size_t)(y0 - 1) * WW + (x0 - 1)) * CC));
        if (yv0 && xv1) v10 = __ldg(reinterpret_cast<const float4*>(base + ((size_t)(y0 - 1) * WW + (x0    )) * CC));
        if (yv1 && xv0) v01 = __ldg(reinterpret_cast<const float4*>(base + ((size_t)(y0    ) * WW + (x0 - 1)) * CC));
        if (yv1 && xv1) v11 = __ldg(reinterpret_cast<const float4*>(base + ((size_t)(y0    ) * WW + (x0    )) * CC));

        const float w00 = (1.f - fx) * (1.f - fy) * m;
        const float w10 = fx * (1.f - fy) * m;
        const float w01 = (1.f - fx) * fy * m;
        const float w11 = fx * fy * m;
        acc.x += v00.x * w00 + v10.x * w10 + v01.x * w01 + v11.x * w11;
        acc.y += v00.y * w00 + v10.y * w10 + v01.y * w01 + v11.y * w11;
        acc.z += v00.z * w00 + v10.z * w10 + v01.z * w01 + v11.z * w11;
        acc.w += v00.w * w00 + v10.w * w10 + v01.w * w01 + v11.w * w11;
    }
    *reinterpret_cast<float4*>(out + (size_t)pos * CC + g * GCC + c4) = acc;
}

// ===========================================================================
extern "C" void kernel_launch(void* const* d_in, const int* in_sizes, int n_in,
                              void* d_out, int out_size) {
    const float* x         = (const float*)d_in[0];
    const float* conv_w    = (const float*)d_in[1];
    const float* conv_b    = (const float*)d_in[2];
    const float* in_proj_w = (const float*)d_in[3];
    const float* in_proj_b = (const float*)d_in[4];
    const float* dw_w      = (const float*)d_in[5];
    const float* dw_b      = (const float*)d_in[6];
    const float* ln_g      = (const float*)d_in[7];
    const float* ln_b      = (const float*)d_in[8];
    const float* off_w     = (const float*)d_in[9];
    const float* off_b     = (const float*)d_in[10];
    const float* mask_w    = (const float*)d_in[11];
    const float* mask_b    = (const float*)d_in[12];
    const float* out_w     = (const float*)d_in[13];
    const float* out_b     = (const float*)d_in[14];
    float* out = (float*)d_out;

    float *xt, *y, *xproj, *dg, *samp, *omp, *w1T, *w2P, *w3T, *b2;
    cudaGetSymbolAddress((void**)&xt,    g_xt);
    cudaGetSymbolAddress((void**)&y,     g_y);
    cudaGetSymbolAddress((void**)&xproj, g_xproj);
    cudaGetSymbolAddress((void**)&dg,    g_dg);
    cudaGetSymbolAddress((void**)&samp,  g_samp);
    cudaGetSymbolAddress((void**)&omp,   g_om);
    cudaGetSymbolAddress((void**)&w1T,   g_w1T);
    cudaGetSymbolAddress((void**)&w2P,   g_w2P);
    cudaGetSymbolAddress((void**)&w3T,   g_w3T);
    cudaGetSymbolAddress((void**)&b2,    g_b2);

    static bool attr_done = false;
    if (!attr_done) {
        cudaFuncSetAttribute(hmma_gemm_kernel,
                             cudaFuncAttributeMaxDynamicSharedMemorySize, GEMM_SMEM);
        attr_done = true;
    }

    const dim3 tblk(32, 32);
    const dim3 tgrid(2, 4, BB * HH);
    const dim3 ggrid(NPOS / 128, 2);

    // 1. weight prep
    prep_weights_kernel<<<CC, CC>>>(in_proj_w, out_w, off_w, mask_w, off_b, mask_b,
                                    w1T, w3T, w2P, b2);
    // 2. pack x: NCHW -> NHWC with zero border (pad=1)
    pack_x_kernel<<<tgrid, tblk>>>(x, xt);
    // 3. 1x1 conv
    hmma_gemm_kernel<<<ggrid, 256, GEMM_SMEM>>>(xt, conv_w, conv_b, y);
    // 4. in_proj
    hmma_gemm_kernel<<<ggrid, 256, GEMM_SMEM>>>(y, w1T, in_proj_b, xproj);
    // 5. depthwise 3x3 + LN + GELU
    dw_ln_gelu_kernel<<<NPOS / 8, 256>>>(y, dw_w, dw_b, ln_g, ln_b, dg);
    // 6. fused offset+mask GEMM (softmax fused into sampler)
    hmma_gemm_kernel<<<ggrid, 256, GEMM_SMEM>>>(dg, w2P, b2, omp);
    // 7. deformable bilinear sampling
    sampler_kernel<<<NPOS / 4, 128>>>(xproj, omp, samp);
    // 8. out_proj (reuse xt as NHWC output buffer)
    hmma_gemm_kernel<<<ggrid, 256, GEMM_SMEM>>>(samp, w3T, out_b, xt);
    // 9. NHWC -> NCHW final output
    unpack_out_kernel<<<tgrid, tblk>>>(xt, out);
}

// round 8
// speedup vs baseline: 2.6740x; 1.1215x over previous
#include <cuda_runtime.h>
#include <math.h>
#include <cstdint>

// Problem constants
#define BB    8
#define CC    128
#define HIN   62
#define HH    64
#define WW    64
#define GG    4
#define GCC   32
#define PP    9
#define NPOS  (BB*HH*WW)   // 32768

// Scratch (device globals; no allocation allowed)
__device__ float g_xt[NPOS*CC];      // x padded+transposed NHWC
__device__ float g_y[NPOS*CC];       // conv1x1 output NHWC
__device__ float g_xproj[NPOS*CC];   // in_proj output NHWC
__device__ float g_dg[NPOS*CC];      // dw+LN+GELU output NHWC
__device__ float g_samp[NPOS*CC];    // sampled output NHWC
__device__ float g_om[NPOS*CC];      // fused offset(72)+mask-logits(36)+pad
__device__ float g_w1T[CC*CC];       // in_proj_w transposed  [n][k]
__device__ float g_w2P[CC*CC];       // fused off/mask weights [n][k], padded
__device__ float g_w3T[CC*CC];       // out_proj_w transposed [n][k]
__device__ float g_b2[CC];           // fused off/mask bias, padded

// ===========================================================================
__device__ __forceinline__ uint32_t f2tf32(float f) {
    uint32_t r;
    asm("cvt.rna.tf32.f32 %0, %1;" : "=r"(r) : "f"(f));
    return r;
}
__device__ __forceinline__ void mma_tf32(float* c, const uint32_t* a, const uint32_t* b) {
    asm volatile(
        "mma.sync.aligned.m16n8k8.row.col.f32.tf32.tf32.f32 "
        "{%0,%1,%2,%3}, {%4,%5,%6,%7}, {%8,%9}, {%0,%1,%2,%3};"
        : "+f"(c[0]), "+f"(c[1]), "+f"(c[2]), "+f"(c[3])
        : "r"(a[0]), "r"(a[1]), "r"(a[2]), "r"(a[3]), "r"(b[0]), "r"(b[1]));
}

// ===========================================================================
// Weight prep: transposes + fused/padded offset-mask weight
// ===========================================================================
__global__ void prep_weights_kernel(const float* __restrict__ w1, const float* __restrict__ w3,
                                    const float* __restrict__ offw, const float* __restrict__ maskw,
                                    const float* __restrict__ offb, const float* __restrict__ maskb,
                                    float* __restrict__ w1T, float* __restrict__ w3T,
                                    float* __restrict__ w2P, float* __restrict__ b2) {
    const int n = blockIdx.x, k = threadIdx.x;
    w1T[n * CC + k] = w1[k * CC + n];
    w3T[n * CC + k] = w3[k * CC + n];
    float v = 0.f;
    if (n < 72)       v = offw[k * 72 + n];
    else if (n < 108) v = maskw[k * 36 + (n - 72)];
    w2P[n * CC + k] = v;
    if (k == 0) b2[n] = (n < 72) ? offb[n] : ((n < 108) ? maskb[n - 72] : 0.f);
}

// ===========================================================================
// x NCHW [8,128,62,62] -> NHWC [8,64,64,128] with 1-px zero border
// ===========================================================================
__global__ void pack_x_kernel(const float* __restrict__ x, float* __restrict__ xt) {
    __shared__ float t[32][33];
    const int b  = blockIdx.z >> 6;
    const int h  = blockIdx.z & 63;
    const int w0 = blockIdx.x * 32;
    const int c0 = blockIdx.y * 32;
    const int tx = threadIdx.x, ty = threadIdx.y;
    const int hh = h - 1;
    const int ww = w0 + tx - 1;
    const int cc = c0 + ty;
    float v = 0.f;
    if (hh >= 0 && hh < HIN && ww >= 0 && ww < HIN)
        v = x[(((size_t)b * CC + cc) * HIN + hh) * HIN + ww];
    t[ty][tx] = v;
    __syncthreads();
    xt[(((size_t)b * HH + h) * WW + (w0 + ty)) * CC + (c0 + tx)] = t[tx][ty];
}

// ===========================================================================
// HMMA tf32 GEMM, split-N: C[M,128] = A[M,128] @ B^T + bias, B given [n][k].
// CTA = 256 threads = 8 warps (4m x 2n). CTA tile = 128 rows x 64 cols.
// TO_NCHW=true: epilogue transposes through smem and writes NCHW directly.
// ===========================================================================
#define SPITCH 132
#define GEMM_SMEM ((CC * SPITCH + 64 * SPITCH) * 4)

template <bool TO_NCHW>
__global__ void __launch_bounds__(256, 2)
hmma_gemm_kernel(const float* __restrict__ A, const float* __restrict__ Bm,
                 const float* __restrict__ bias, float* __restrict__ Cout) {
    extern __shared__ float smem[];
    float* sA = smem;                 // [128][132]
    float* sB = smem + CC * SPITCH;   // [64][132]

    const int tid  = threadIdx.x;
    const int lane = tid & 31;
    const int wid  = tid >> 5;
    const int gid  = lane >> 2;   // 0..7
    const int tg   = lane & 3;    // 0..3
    const int warp_m = wid & 3;   // 0..3  (32 rows each)
    const int warp_n = wid >> 2;  // 0..1  (32 cols each)
    const int m0 = blockIdx.x * 128;
    const int n0 = blockIdx.y * 64;

    #pragma unroll
    for (int i = 0; i < 16; i++) {
        const int idx = i * 256 + tid;
        const int row = idx >> 5;
        const int c4  = idx & 31;
        float4 va = *reinterpret_cast<const float4*>(A + (size_t)(m0 + row) * CC + c4 * 4);
        uint4 ta;
        ta.x = f2tf32(va.x); ta.y = f2tf32(va.y); ta.z = f2tf32(va.z); ta.w = f2tf32(va.w);
        *reinterpret_cast<uint4*>(sA + row * SPITCH + c4 * 4) = ta;
    }
    #pragma unroll
    for (int i = 0; i < 8; i++) {
        const int idx = i * 256 + tid;
        const int row = idx >> 5;
        const int c4  = idx & 31;
        float4 vb = *reinterpret_cast<const float4*>(Bm + (size_t)(n0 + row) * CC + c4 * 4);
        uint4 tb;
        tb.x = f2tf32(vb.x); tb.y = f2tf32(vb.y); tb.z = f2tf32(vb.z); tb.w = f2tf32(vb.w);
        *reinterpret_cast<uint4*>(sB + row * SPITCH + c4 * 4) = tb;
    }
    __syncthreads();

    float acc[2][4][4];
    #pragma unroll
    for (int mi = 0; mi < 2; mi++)
        #pragma unroll
        for (int ni = 0; ni < 4; ni++)
            #pragma unroll
            for (int j = 0; j < 4; j++) acc[mi][ni][j] = 0.f;

    const uint32_t* uA = reinterpret_cast<const uint32_t*>(sA);
    const uint32_t* uB = reinterpret_cast<const uint32_t*>(sB);
    const int arow0 = warp_m * 32 + gid;
    const int bcol0 = warp_n * 32 + gid;

    #pragma unroll 4
    for (int ks = 0; ks < 16; ks++) {
        const int k8 = ks * 8;
        uint32_t af[2][4];
        #pragma unroll
        for (int mi = 0; mi < 2; mi++) {
            const int r = arow0 + mi * 16;
            af[mi][0] = uA[(r    ) * SPITCH + k8 + tg];
            af[mi][1] = uA[(r + 8) * SPITCH + k8 + tg];
            af[mi][2] = uA[(r    ) * SPITCH + k8 + tg + 4];
            af[mi][3] = uA[(r + 8) * SPITCH + k8 + tg + 4];
        }
        #pragma unroll
        for (int ni = 0; ni < 4; ni++) {
            uint32_t bf[2];
            const int n = bcol0 + ni * 8;
            bf[0] = uB[n * SPITCH + k8 + tg];
            bf[1] = uB[n * SPITCH + k8 + tg + 4];
            mma_tf32(acc[0][ni], af[0], bf);
            mma_tf32(acc[1][ni], af[1], bf);
        }
    }

    float2 bb[4];
    #pragma unroll
    for (int ni = 0; ni < 4; ni++) {
        const int col = n0 + warp_n * 32 + ni * 8 + 2 * tg;
        bb[ni].x = __ldg(bias + col);
        bb[ni].y = __ldg(bias + col + 1);
    }

    if (!TO_NCHW) {
        #pragma unroll
        for (int mi = 0; mi < 2; mi++) {
            const int r0 = m0 + arow0 + mi * 16;
            #pragma unroll
            for (int ni = 0; ni < 4; ni++) {
                const int col = n0 + warp_n * 32 + ni * 8 + 2 * tg;
                float2 v0 = make_float2(acc[mi][ni][0] + bb[ni].x, acc[mi][ni][1] + bb[ni].y);
                float2 v1 = make_float2(acc[mi][ni][2] + bb[ni].x, acc[mi][ni][3] + bb[ni].y);
                *reinterpret_cast<float2*>(Cout + (size_t)r0 * CC + col)       = v0;
                *reinterpret_cast<float2*>(Cout + (size_t)(r0 + 8) * CC + col) = v1;
            }
        }
    } else {
        // Stage transposed into sA region: sCT[col 0..63][row 0..127], pitch 132.
        __syncthreads();   // done reading sA/sB
        float* sCT = smem;
        #pragma unroll
        for (int mi = 0; mi < 2; mi++) {
            #pragma unroll
            for (int ni = 0; ni < 4; ni++) {
                const int col = warp_n * 32 + ni * 8 + 2 * tg;   // local col
                const int r   = arow0 + mi * 16;                 // local row
                sCT[(col    ) * SPITCH + r    ] = acc[mi][ni][0] + bb[ni].x;
                sCT[(col + 1) * SPITCH + r    ] = acc[mi][ni][1] + bb[ni].y;
                sCT[(col    ) * SPITCH + r + 8] = acc[mi][ni][2] + bb[ni].x;
                sCT[(col + 1) * SPITCH + r + 8] = acc[mi][ni][3] + bb[ni].y;
            }
        }
        __syncthreads();
        // Write NCHW: channel = n0+col; 128 consecutive positions are contiguous.
        const int b       = m0 >> 12;
        const int inbatch = m0 & 4095;
        #pragma unroll
        for (int i = 0; i < 8; i++) {
            const int idx = i * 256 + tid;      // 0..2047 float4s
            const int col = idx >> 5;
            const int rc  = idx & 31;
            const float4 v = *reinterpret_cast<const float4*>(sCT + col * SPITCH + rc * 4);
            *reinterpret_cast<float4*>(
                Cout + ((size_t)b * CC + (n0 + col)) * (HH * WW) + inbatch + rc * 4) = v;
        }
    }
}

// ===========================================================================
// Depthwise 3x3 (pad 1) + bias + LayerNorm(C) + exact GELU.
// ===========================================================================
__global__ void __launch_bounds__(256)
dw_ln_gelu_kernel(const float* __restrict__ y,
                  const float* __restrict__ dww,
                  const float* __restrict__ dwb,
                  const float* __restrict__ lng,
                  const float* __restrict__ lnb,
                  float* __restrict__ out) {
    __shared__ float sW[9 * CC];   // transposed: [tap][c]
    const int tid = threadIdx.x;
    for (int i = tid; i < 9 * CC; i += 256) {
        const int c = i / 9, tap = i % 9;
        sW[tap * CC + c] = dww[i];
    }
    __syncthreads();

    const int wid  = tid >> 5;
    const int lane = tid & 31;
    const int pos  = blockIdx.x * 8 + wid;
    const int b = pos >> 12;
    const int h = (pos >> 6) & 63;
    const int w = pos & 63;
    const int c4 = lane * 4;

    const float4 bv = __ldg(reinterpret_cast<const float4*>(dwb + c4));
    float4 acc = bv;
    const float* ybase = y + (((size_t)b * HH + h) * WW + w) * CC + c4;
    #pragma unroll
    for (int i = 0; i < 3; i++) {
        const int hh = h + i - 1;
        if ((unsigned)hh >= (unsigned)HH) continue;
        #pragma unroll
        for (int j = 0; j < 3; j++) {
            const int ww = w + j - 1;
            if ((unsigned)ww >= (unsigned)WW) continue;
            const float4 v = __ldg(reinterpret_cast<const float4*>(
                ybase + ((i - 1) * WW + (j - 1)) * CC));
            const float4 wt = *reinterpret_cast<const float4*>(sW + (i * 3 + j) * CC + c4);
            acc.x = fmaf(v.x, wt.x, acc.x);
            acc.y = fmaf(v.y, wt.y, acc.y);
            acc.z = fmaf(v.z, wt.z, acc.z);
            acc.w = fmaf(v.w, wt.w, acc.w);
        }
    }

    float s  = acc.x + acc.y + acc.z + acc.w;
    float s2 = acc.x * acc.x + acc.y * acc.y + acc.z * acc.z + acc.w * acc.w;
    #pragma unroll
    for (int o = 16; o > 0; o >>= 1) {
        s  += __shfl_xor_sync(0xFFFFFFFFu, s,  o);
        s2 += __shfl_xor_sync(0xFFFFFFFFu, s2, o);
    }
    const float mean = s * (1.f / CC);
    const float var  = s2 * (1.f / CC) - mean * mean;
    const float rstd = rsqrtf(var + 1e-5f);

    const float4 gv = __ldg(reinterpret_cast<const float4*>(lng + c4));
    const float4 betav = __ldg(reinterpret_cast<const float4*>(lnb + c4));
    float4 o4;
    {
        float v0 = (acc.x - mean) * rstd * gv.x + betav.x;
        float v1 = (acc.y - mean) * rstd * gv.y + betav.y;
        float v2 = (acc.z - mean) * rstd * gv.z + betav.z;
        float v3 = (acc.w - mean) * rstd * gv.w + betav.w;
        const float k = 0.70710678118654752440f;
        o4.x = 0.5f * v0 * (1.f + erff(v0 * k));
        o4.y = 0.5f * v1 * (1.f + erff(v1 * k));
        o4.z = 0.5f * v2 * (1.f + erff(v2 * k));
        o4.w = 0.5f * v3 * (1.f + erff(v3 * k));
    }
    *reinterpret_cast<float4*>(out + (size_t)pos * CC + c4) = o4;
}

// ===========================================================================
// DCNv3 bilinear sampler + fused group softmax.
// ===========================================================================
__global__ void __launch_bounds__(128)
sampler_kernel(const float* __restrict__ xproj,
               const float* __restrict__ om,
               float* __restrict__ out) {
    __shared__ float sOM[4][112];
    const int tid  = threadIdx.x;
    const int wid  = tid >> 5;
    const int lane = tid & 31;
    const int pos  = blockIdx.x * 4 + wid;
    const int b = pos >> 12;
    const int h = (pos >> 6) & 63;
    const int w = pos & 63;
    const int g  = lane >> 3;
    const int c4 = (lane & 7) * 4;

    #pragma unroll
    for (int r = 0; r < 4; r++) {
        const int i = r * 32 + lane;
        if (i < 108) sOM[wid][i] = __ldg(om + (size_t)pos * CC + i);
    }
    __syncwarp();

    const float* logit = &sOM[wid][72 + g * 9];
    float mx = -1e30f;
    #pragma unroll
    for (int p = 0; p < 9; p++) mx = fmaxf(mx, logit[p]);
    float se = 0.f;
    float ex[9];
    #pragma unroll
    for (int p = 0; p < 9; p++) { ex[p] = expf(logit[p] - mx); se += ex[p]; }
    const float inv_se = 1.f / se;

    const float* base = xproj + (size_t)b * (HH * WW * CC) + g * GCC + c4;
    float4 acc = make_float4(0.f, 0.f, 0.f, 0.f);
    #pragma unroll
    for (int p = 0; p < PP; p++) {
        const int gp = g * 9 + p;
        const float fix = (float)(w + p / 3) + sOM[wid][2 * gp];
        const float fiy = (float)(h + p % 3) + sOM[wid][2 * gp + 1];
        const float x0f = floorf(fix), y0f = floorf(fiy);
        const float fx = fix - x0f, fy = fiy - y0f;
        const int x0 = (int)x0f, y0 = (int)y0f;
        const float m = ex[p] * inv_se;

        const bool xv0 = (x0 >= 1) && (x0 <= 64);
        const bool xv1 = (x0 >= 0) && (x0 <= 63);
        const bool yv0 = (y0 >= 1) && (y0 <= 64);
        const bool yv1 = (y0 >= 0) && (y0 <= 63);
        float4 v00 = make_float4(0,0,0,0), v10 = v00, v01 = v00, v11 = v00;
        if (yv0 && xv0) v00 = __ldg(reinterpret_cast<const float4*>(base + ((size_t)(y0 - 1) * WW + (x0 - 1)) * CC));
        if (yv0 && xv1) v10 = __ldg(reinterpret_cast<const float4*>(base + ((size_t)(y0 - 1) * WW + (x0    )) * CC));
        if (yv1 && xv0) v01 = __ldg(reinterpret_cast<const float4*>(base + ((size_t)(y0    ) * WW + (x0 - 1)) * CC));
        if (yv1 && xv1) v11 = __ldg(reinterpret_cast<const float4*>(base + ((size_t)(y0    ) * WW + (x0    )) * CC));

        const float w00 = (1.f - fx) * (1.f - fy) * m;
        const float w10 = fx * (1.f - fy) * m;
        const float w01 = (1.f - fx) * fy * m;
        const float w11 = fx * fy * m;
        acc.x += v00.x * w00 + v10.x * w10 + v01.x * w01 + v11.x * w11;
        acc.y += v00.y * w00 + v10.y * w10 + v01.y * w01 + v11.y * w11;
        acc.z += v00.z * w00 + v10.z * w10 + v01.z * w01 + v11.z * w11;
        acc.w += v00.w * w00 + v10.w * w10 + v01.w * w01 + v11.w * w11;
    }
    *reinterpret_cast<float4*>(out + (size_t)pos * CC + g * GCC + c4) = acc;
}

// ===========================================================================
extern "C" void kernel_launch(void* const* d_in, const int* in_sizes, int n_in,
                              void* d_out, int out_size) {
    const float* x         = (const float*)d_in[0];
    const float* conv_w    = (const float*)d_in[1];
    const float* conv_b    = (const float*)d_in[2];
    const float* in_proj_w = (const float*)d_in[3];
    const float* in_proj_b = (const float*)d_in[4];
    const float* dw_w      = (const float*)d_in[5];
    const float* dw_b      = (const float*)d_in[6];
    const float* ln_g      = (const float*)d_in[7];
    const float* ln_b      = (const float*)d_in[8];
    const float* off_w     = (const float*)d_in[9];
    const float* off_b     = (const float*)d_in[10];
    const float* mask_w    = (const float*)d_in[11];
    const float* mask_b    = (const float*)d_in[12];
    const float* out_w     = (const float*)d_in[13];
    const float* out_b     = (const float*)d_in[14];
    float* out = (float*)d_out;

    float *xt, *y, *xproj, *dg, *samp, *omp, *w1T, *w2P, *w3T, *b2;
    cudaGetSymbolAddress((void**)&xt,    g_xt);
    cudaGetSymbolAddress((void**)&y,     g_y);
    cudaGetSymbolAddress((void**)&xproj, g_xproj);
    cudaGetSymbolAddress((void**)&dg,    g_dg);
    cudaGetSymbolAddress((void**)&samp,  g_samp);
    cudaGetSymbolAddress((void**)&omp,   g_om);
    cudaGetSymbolAddress((void**)&w1T,   g_w1T);
    cudaGetSymbolAddress((void**)&w2P,   g_w2P);
    cudaGetSymbolAddress((void**)&w3T,   g_w3T);
    cudaGetSymbolAddress((void**)&b2,    g_b2);

    static cudaStream_t s1 = nullptr;
    static cudaEvent_t eFork = nullptr, ePrep = nullptr, eConv = nullptr, eProj = nullptr;
    static bool init_done = false;
    if (!init_done) {
        cudaFuncSetAttribute(hmma_gemm_kernel<false>,
                             cudaFuncAttributeMaxDynamicSharedMemorySize, GEMM_SMEM);
        cudaFuncSetAttribute(hmma_gemm_kernel<true>,
                             cudaFuncAttributeMaxDynamicSharedMemorySize, GEMM_SMEM);
        cudaStreamCreateWithFlags(&s1, cudaStreamNonBlocking);
        cudaEventCreateWithFlags(&eFork, cudaEventDisableTiming);
        cudaEventCreateWithFlags(&ePrep, cudaEventDisableTiming);
        cudaEventCreateWithFlags(&eConv, cudaEventDisableTiming);
        cudaEventCreateWithFlags(&eProj, cudaEventDisableTiming);
        init_done = true;
    }

    const dim3 tblk(32, 32);
    const dim3 tgrid(2, 4, BB * HH);
    const dim3 ggrid(NPOS / 128, 2);

    // ---- fork side stream from the capture-origin (default) stream ----
    cudaEventRecord(eFork, 0);
    cudaStreamWaitEvent(s1, eFork, 0);

    // s1: weight prep (needed by in_proj on s1; off_mask/out_proj on s0 wait ePrep)
    prep_weights_kernel<<<CC, CC, 0, s1>>>(in_proj_w, out_w, off_w, mask_w, off_b, mask_b,
                                           w1T, w3T, w2P, b2);
    cudaEventRecord(ePrep, s1);

    // s0: pack + conv
    pack_x_kernel<<<tgrid, tblk>>>(x, xt);
    hmma_gemm_kernel<false><<<ggrid, 256, GEMM_SMEM>>>(xt, conv_w, conv_b, y);
    cudaEventRecord(eConv, 0);

    // s1: in_proj (independent of the dw/off_mask branch)
    cudaStreamWaitEvent(s1, eConv, 0);
    hmma_gemm_kernel<false><<<ggrid, 256, GEMM_SMEM, s1>>>(y, w1T, in_proj_b, xproj);
    cudaEventRecord(eProj, s1);

    // s0: dw+LN+GELU -> off_mask GEMM
    dw_ln_gelu_kernel<<<NPOS / 8, 256>>>(y, dw_w, dw_b, ln_g, ln_b, dg);
    cudaStreamWaitEvent(0, ePrep, 0);
    hmma_gemm_kernel<false><<<ggrid, 256, GEMM_SMEM>>>(dg, w2P, b2, omp);

    // join: sampler needs xproj (s1) + omp (s0)
    cudaStreamWaitEvent(0, eProj, 0);
    sampler_kernel<<<NPOS / 4, 128>>>(xproj, omp, samp);

    // out_proj writes NCHW directly (unpack fused into epilogue)
    hmma_gemm_kernel<true><<<ggrid, 256, GEMM_SMEM>>>(samp, w3T, out_b, out);
}

// round 9
// speedup vs baseline: 2.7602x; 1.0322x over previous
#include <cuda_runtime.h>
#include <math.h>
#include <cstdint>

// Problem constants
#define BB    8
#define CC    128
#define HIN   62
#define HH    64
#define WW    64
#define GG    4
#define GCC   32
#define PP    9
#define NPOS  (BB*HH*WW)   // 32768

// Scratch (device globals; no allocation allowed)
__device__ float g_xt[NPOS*CC];
__device__ float g_y[NPOS*CC];
__device__ float g_xproj[NPOS*CC];
__device__ float g_dg[NPOS*CC];
__device__ float g_samp[NPOS*CC];
__device__ float g_om[NPOS*CC];
__device__ float g_w1T[CC*CC];
__device__ float g_w2P[CC*CC];
__device__ float g_w3T[CC*CC];
__device__ float g_b2[CC];

// ===========================================================================
__device__ __forceinline__ uint32_t f2tf32(float f) {
    uint32_t r;
    asm("cvt.rna.tf32.f32 %0, %1;" : "=r"(r) : "f"(f));
    return r;
}
__device__ __forceinline__ void mma_tf32(float* c, const uint32_t* a, const uint32_t* b) {
    asm volatile(
        "mma.sync.aligned.m16n8k8.row.col.f32.tf32.tf32.f32 "
        "{%0,%1,%2,%3}, {%4,%5,%6,%7}, {%8,%9}, {%0,%1,%2,%3};"
        : "+f"(c[0]), "+f"(c[1]), "+f"(c[2]), "+f"(c[3])
        : "r"(a[0]), "r"(a[1]), "r"(a[2]), "r"(a[3]), "r"(b[0]), "r"(b[1]));
}
__device__ __forceinline__ uint32_t smem_u32(const void* p) {
    uint32_t a;
    asm("{ .reg .u64 t; cvta.to.shared.u64 t, %1; cvt.u32.u64 %0, t; }" : "=r"(a) : "l"(p));
    return a;
}
#define CP_ASYNC16(dst, src) \
    asm volatile("cp.async.cg.shared.global [%0], [%1], 16;" \
        :: "r"(dst), "l"(__cvta_generic_to_global(src)) : "memory")
#define CP_COMMIT() asm volatile("cp.async.commit_group;" ::: "memory")
#define CP_WAIT(n)  asm volatile("cp.async.wait_group %0;" :: "n"(n) : "memory")

// ===========================================================================
// Weight prep
// ===========================================================================
__global__ void prep_weights_kernel(const float* __restrict__ w1, const float* __restrict__ w3,
                                    const float* __restrict__ offw, const float* __restrict__ maskw,
                                    const float* __restrict__ offb, const float* __restrict__ maskb,
                                    float* __restrict__ w1T, float* __restrict__ w3T,
                                    float* __restrict__ w2P, float* __restrict__ b2) {
    const int n = blockIdx.x, k = threadIdx.x;
    w1T[n * CC + k] = w1[k * CC + n];
    w3T[n * CC + k] = w3[k * CC + n];
    float v = 0.f;
    if (n < 72)       v = offw[k * 72 + n];
    else if (n < 108) v = maskw[k * 36 + (n - 72)];
    w2P[n * CC + k] = v;
    if (k == 0) b2[n] = (n < 72) ? offb[n] : ((n < 108) ? maskb[n - 72] : 0.f);
}

// ===========================================================================
// x NCHW -> NHWC with 1-px zero border
// ===========================================================================
__global__ void pack_x_kernel(const float* __restrict__ x, float* __restrict__ xt) {
    __shared__ float t[32][33];
    const int b  = blockIdx.z >> 6;
    const int h  = blockIdx.z & 63;
    const int w0 = blockIdx.x * 32;
    const int c0 = blockIdx.y * 32;
    const int tx = threadIdx.x, ty = threadIdx.y;
    const int hh = h - 1;
    const int ww = w0 + tx - 1;
    const int cc = c0 + ty;
    float v = 0.f;
    if (hh >= 0 && hh < HIN && ww >= 0 && ww < HIN)
        v = x[(((size_t)b * CC + cc) * HIN + hh) * HIN + ww];
    t[ty][tx] = v;
    __syncthreads();
    xt[(((size_t)b * HH + h) * WW + (w0 + ty)) * CC + (c0 + tx)] = t[tx][ty];
}

// ===========================================================================
// HMMA tf32 GEMM, split-N + cp.async double-buffered K-chunks.
// CTA = 256 threads (4m x 2n warps); tile = 128 rows x 64 cols; K chunk = 64.
// smem: per stage A[128][68] + B[64][68]; 2 stages = 104448 B -> 2 CTAs/SM.
// TO_NCHW=true: epilogue transposes through smem, writes NCHW directly.
// ===========================================================================
#define CH      64
#define CPITCH  68
#define STAGE_F (192 * CPITCH)            // floats per stage
#define GEMM_SMEM (2 * STAGE_F * 4)       // 104448 bytes
#define SPITCH  132                        // epilogue staging pitch

template <bool TO_NCHW>
__global__ void __launch_bounds__(256, 2)
hmma_gemm_kernel(const float* __restrict__ A, const float* __restrict__ Bm,
                 const float* __restrict__ bias, float* __restrict__ Cout) {
    extern __shared__ float smem[];
    const uint32_t sbase = smem_u32(smem);

    const int tid  = threadIdx.x;
    const int lane = tid & 31;
    const int wid  = tid >> 5;
    const int gid  = lane >> 2;
    const int tg   = lane & 3;
    const int warp_m = wid & 3;
    const int warp_n = wid >> 2;
    const int m0 = blockIdx.x * 128;
    const int n0 = blockIdx.y * 64;

    // ---- issue one K-chunk into stage s (12 cp.async.16 per thread) ----
    const int irow_a = tid >> 4;          // A rows handled: irow_a, +16, ...
    const int ic     = (tid & 15) * 4;    // float offset within chunk row
    auto issue = [&](int s, int kc) {
        const uint32_t st = sbase + (uint32_t)(s * STAGE_F * 4);
        #pragma unroll
        for (int i = 0; i < 8; i++) {
            const int row = irow_a + i * 16;
            const float* src = A + (size_t)(m0 + row) * CC + kc + ic;
            CP_ASYNC16(st + (uint32_t)((row * CPITCH + ic) * 4), src);
        }
        #pragma unroll
        for (int i = 0; i < 4; i++) {
            const int row = irow_a + i * 16;
            if (row < 64) {
                const float* src = Bm + (size_t)(n0 + row) * CC + kc + ic;
                CP_ASYNC16(st + (uint32_t)(((128 + row) * CPITCH + ic) * 4), src);
            }
        }
        CP_COMMIT();
    };

    issue(0, 0);
    issue(1, CH);

    float acc[2][4][4];
    #pragma unroll
    for (int mi = 0; mi < 2; mi++)
        #pragma unroll
        for (int ni = 0; ni < 4; ni++)
            #pragma unroll
            for (int j = 0; j < 4; j++) acc[mi][ni][j] = 0.f;

    const int arow0 = warp_m * 32 + gid;
    const int bcol0 = warp_n * 32 + gid;

    // ---- MMA over one staged chunk (8 k-steps of 8) ----
    auto mma_chunk = [&](int s) {
        const float* uA = smem + s * STAGE_F;
        const float* uB = uA + 128 * CPITCH;
        #pragma unroll
        for (int ks = 0; ks < 8; ks++) {
            const int k8 = ks * 8;
            uint32_t af[2][4];
            #pragma unroll
            for (int mi = 0; mi < 2; mi++) {
                const int r = arow0 + mi * 16;
                af[mi][0] = f2tf32(uA[(r    ) * CPITCH + k8 + tg]);
                af[mi][1] = f2tf32(uA[(r + 8) * CPITCH + k8 + tg]);
                af[mi][2] = f2tf32(uA[(r    ) * CPITCH + k8 + tg + 4]);
                af[mi][3] = f2tf32(uA[(r + 8) * CPITCH + k8 + tg + 4]);
            }
            #pragma unroll
            for (int ni = 0; ni < 4; ni++) {
                const int n = bcol0 + ni * 8;
                uint32_t bf[2];
                bf[0] = f2tf32(uB[n * CPITCH + k8 + tg]);
                bf[1] = f2tf32(uB[n * CPITCH + k8 + tg + 4]);
                mma_tf32(acc[0][ni], af[0], bf);
                mma_tf32(acc[1][ni], af[1], bf);
            }
        }
    };

    CP_WAIT(1);
    __syncthreads();
    mma_chunk(0);
    CP_WAIT(0);
    __syncthreads();
    mma_chunk(1);

    float2 bb[4];
    #pragma unroll
    for (int ni = 0; ni < 4; ni++) {
        const int col = n0 + warp_n * 32 + ni * 8 + 2 * tg;
        bb[ni].x = __ldg(bias + col);
        bb[ni].y = __ldg(bias + col + 1);
    }

    if (!TO_NCHW) {
        #pragma unroll
        for (int mi = 0; mi < 2; mi++) {
            const int r0 = m0 + arow0 + mi * 16;
            #pragma unroll
            for (int ni = 0; ni < 4; ni++) {
                const int col = n0 + warp_n * 32 + ni * 8 + 2 * tg;
                float2 v0 = make_float2(acc[mi][ni][0] + bb[ni].x, acc[mi][ni][1] + bb[ni].y);
                float2 v1 = make_float2(acc[mi][ni][2] + bb[ni].x, acc[mi][ni][3] + bb[ni].y);
                *reinterpret_cast<float2*>(Cout + (size_t)r0 * CC + col)       = v0;
                *reinterpret_cast<float2*>(Cout + (size_t)(r0 + 8) * CC + col) = v1;
            }
        }
    } else {
        __syncthreads();   // all warps done reading stage buffers
        float* sCT = smem;  // [64 cols][128 rows], pitch 132
        #pragma unroll
        for (int mi = 0; mi < 2; mi++) {
            #pragma unroll
            for (int ni = 0; ni < 4; ni++) {
                const int col = warp_n * 32 + ni * 8 + 2 * tg;
                const int r   = arow0 + mi * 16;
                sCT[(col    ) * SPITCH + r    ] = acc[mi][ni][0] + bb[ni].x;
                sCT[(col + 1) * SPITCH + r    ] = acc[mi][ni][1] + bb[ni].y;
                sCT[(col    ) * SPITCH + r + 8] = acc[mi][ni][2] + bb[ni].x;
                sCT[(col + 1) * SPITCH + r + 8] = acc[mi][ni][3] + bb[ni].y;
            }
        }
        __syncthreads();
        const int b       = m0 >> 12;
        const int inbatch = m0 & 4095;
        #pragma unroll
        for (int i = 0; i < 8; i++) {
            const int idx = i * 256 + tid;
            const int col = idx >> 5;
            const int rc  = idx & 31;
            const float4 v = *reinterpret_cast<const float4*>(sCT + col * SPITCH + rc * 4);
            *reinterpret_cast<float4*>(
                Cout + ((size_t)b * CC + (n0 + col)) * (HH * WW) + inbatch + rc * 4) = v;
        }
    }
}

// ===========================================================================
// Depthwise 3x3 (pad 1) + bias + LayerNorm(C) + exact GELU.
// ===========================================================================
__global__ void __launch_bounds__(256)
dw_ln_gelu_kernel(const float* __restrict__ y,
                  const float* __restrict__ dww,
                  const float* __restrict__ dwb,
                  const float* __restrict__ lng,
                  const float* __restrict__ lnb,
                  float* __restrict__ out) {
    __shared__ float sW[9 * CC];
    const int tid = threadIdx.x;
    for (int i = tid; i < 9 * CC; i += 256) {
        const int c = i / 9, tap = i % 9;
        sW[tap * CC + c] = dww[i];
    }
    __syncthreads();

    const int wid  = tid >> 5;
    const int lane = tid & 31;
    const int pos  = blockIdx.x * 8 + wid;
    const int b = pos >> 12;
    const int h = (pos >> 6) & 63;
    const int w = pos & 63;
    const int c4 = lane * 4;

    const float4 bv = __ldg(reinterpret_cast<const float4*>(dwb + c4));
    float4 acc = bv;
    const float* ybase = y + (((size_t)b * HH + h) * WW + w) * CC + c4;
    #pragma unroll
    for (int i = 0; i < 3; i++) {
        const int hh = h + i - 1;
        if ((unsigned)hh >= (unsigned)HH) continue;
        #pragma unroll
        for (int j = 0; j < 3; j++) {
            const int ww = w + j - 1;
            if ((unsigned)ww >= (unsigned)WW) continue;
            const float4 v = __ldg(reinterpret_cast<const float4*>(
                ybase + ((i - 1) * WW + (j - 1)) * CC));
            const float4 wt = *reinterpret_cast<const float4*>(sW + (i * 3 + j) * CC + c4);
            acc.x = fmaf(v.x, wt.x, acc.x);
            acc.y = fmaf(v.y, wt.y, acc.y);
            acc.z = fmaf(v.z, wt.z, acc.z);
            acc.w = fmaf(v.w, wt.w, acc.w);
        }
    }

    float s  = acc.x + acc.y + acc.z + acc.w;
    float s2 = acc.x * acc.x + acc.y * acc.y + acc.z * acc.z + acc.w * acc.w;
    #pragma unroll
    for (int o = 16; o > 0; o >>= 1) {
        s  += __shfl_xor_sync(0xFFFFFFFFu, s,  o);
        s2 += __shfl_xor_sync(0xFFFFFFFFu, s2, o);
    }
    const float mean = s * (1.f / CC);
    const float var  = s2 * (1.f / CC) - mean * mean;
    const float rstd = rsqrtf(var + 1e-5f);

    const float4 gv = __ldg(reinterpret_cast<const float4*>(lng + c4));
    const float4 betav = __ldg(reinterpret_cast<const float4*>(lnb + c4));
    float4 o4;
    {
        float v0 = (acc.x - mean) * rstd * gv.x + betav.x;
        float v1 = (acc.y - mean) * rstd * gv.y + betav.y;
        float v2 = (acc.z - mean) * rstd * gv.z + betav.z;
        float v3 = (acc.w - mean) * rstd * gv.w + betav.w;
        const float k = 0.70710678118654752440f;
        o4.x = 0.5f * v0 * (1.f + erff(v0 * k));
        o4.y = 0.5f * v1 * (1.f + erff(v1 * k));
        o4.z = 0.5f * v2 * (1.f + erff(v2 * k));
        o4.w = 0.5f * v3 * (1.f + erff(v3 * k));
    }
    *reinterpret_cast<float4*>(out + (size_t)pos * CC + c4) = o4;
}

// ===========================================================================
// DCNv3 bilinear sampler + fused group softmax.
// ===========================================================================
__global__ void __launch_bounds__(128)
sampler_kernel(const float* __restrict__ xproj,
               const float* __restrict__ om,
               float* __restrict__ out) {
    __shared__ float sOM[4][112];
    const int tid  = threadIdx.x;
    const int wid  = tid >> 5;
    const int lane = tid & 31;
    const int pos  = blockIdx.x * 4 + wid;
    const int b = pos >> 12;
    const int h = (pos >> 6) & 63;
    const int w = pos & 63;
    const int g  = lane >> 3;
    const int c4 = (lane & 7) * 4;

    #pragma unroll
    for (int r = 0; r < 4; r++) {
        const int i = r * 32 + lane;
        if (i < 108) sOM[wid][i] = __ldg(om + (size_t)pos * CC + i);
    }
    __syncwarp();

    const float* logit = &sOM[wid][72 + g * 9];
    float mx = -1e30f;
    #pragma unroll
    for (int p = 0; p < 9; p++) mx = fmaxf(mx, logit[p]);
    float se = 0.f;
    float ex[9];
    #pragma unroll
    for (int p = 0; p < 9; p++) { ex[p] = expf(logit[p] - mx); se += ex[p]; }
    const float inv_se = 1.f / se;

    const float* base = xproj + (size_t)b * (HH * WW * CC) + g * GCC + c4;
    float4 acc = make_float4(0.f, 0.f, 0.f, 0.f);
    #pragma unroll
    for (int p = 0; p < PP; p++) {
        const int gp = g * 9 + p;
        const float fix = (float)(w + p / 3) + sOM[wid][2 * gp];
        const float fiy = (float)(h + p % 3) + sOM[wid][2 * gp + 1];
        const float x0f = floorf(fix), y0f = floorf(fiy);
        const float fx = fix - x0f, fy = fiy - y0f;
        const int x0 = (int)x0f, y0 = (int)y0f;
        const float m = ex[p] * inv_se;

        const bool xv0 = (x0 >= 1) && (x0 <= 64);
        const bool xv1 = (x0 >= 0) && (x0 <= 63);
        const bool yv0 = (y0 >= 1) && (y0 <= 64);
        const bool yv1 = (y0 >= 0) && (y0 <= 63);
        float4 v00 = make_float4(0,0,0,0), v10 = v00, v01 = v00, v11 = v00;
        if (yv0 && xv0) v00 = __ldg(reinterpret_cast<const float4*>(base + ((size_t)(y0 - 1) * WW + (x0 - 1)) * CC));
        if (yv0 && xv1) v10 = __ldg(reinterpret_cast<const float4*>(base + ((size_t)(y0 - 1) * WW + (x0    )) * CC));
        if (yv1 && xv0) v01 = __ldg(reinterpret_cast<const float4*>(base + ((size_t)(y0    ) * WW + (x0 - 1)) * CC));
        if (yv1 && xv1) v11 = __ldg(reinterpret_cast<const float4*>(base + ((size_t)(y0    ) * WW + (x0    )) * CC));

        const float w00 = (1.f - fx) * (1.f - fy) * m;
        const float w10 = fx * (1.f - fy) * m;
        const float w01 = (1.f - fx) * fy * m;
        const float w11 = fx * fy * m;
        acc.x += v00.x * w00 + v10.x * w10 + v01.x * w01 + v11.x * w11;
        acc.y += v00.y * w00 + v10.y * w10 + v01.y * w01 + v11.y * w11;
        acc.z += v00.z * w00 + v10.z * w10 + v01.z * w01 + v11.z * w11;
        acc.w += v00.w * w00 + v10.w * w10 + v01.w * w01 + v11.w * w11;
    }
    *reinterpret_cast<float4*>(out + (size_t)pos * CC + g * GCC + c4) = acc;
}

// ===========================================================================
extern "C" void kernel_launch(void* const* d_in, const int* in_sizes, int n_in,
                              void* d_out, int out_size) {
    const float* x         = (const float*)d_in[0];
    const float* conv_w    = (const float*)d_in[1];
    const float* conv_b    = (const float*)d_in[2];
    const float* in_proj_w = (const float*)d_in[3];
    const float* in_proj_b = (const float*)d_in[4];
    const float* dw_w      = (const float*)d_in[5];
    const float* dw_b      = (const float*)d_in[6];
    const float* ln_g      = (const float*)d_in[7];
    const float* ln_b      = (const float*)d_in[8];
    const float* off_w     = (const float*)d_in[9];
    const float* off_b     = (const float*)d_in[10];
    const float* mask_w    = (const float*)d_in[11];
    const float* mask_b    = (const float*)d_in[12];
    const float* out_w     = (const float*)d_in[13];
    const float* out_b     = (const float*)d_in[14];
    float* out = (float*)d_out;

    float *xt, *y, *xproj, *dg, *samp, *omp, *w1T, *w2P, *w3T, *b2;
    cudaGetSymbolAddress((void**)&xt,    g_xt);
    cudaGetSymbolAddress((void**)&y,     g_y);
    cudaGetSymbolAddress((void**)&xproj, g_xproj);
    cudaGetSymbolAddress((void**)&dg,    g_dg);
    cudaGetSymbolAddress((void**)&samp,  g_samp);
    cudaGetSymbolAddress((void**)&omp,   g_om);
    cudaGetSymbolAddress((void**)&w1T,   g_w1T);
    cudaGetSymbolAddress((void**)&w2P,   g_w2P);
    cudaGetSymbolAddress((void**)&w3T,   g_w3T);
    cudaGetSymbolAddress((void**)&b2,    g_b2);

    static cudaStream_t s1 = nullptr;
    static cudaEvent_t eFork = nullptr, ePrep = nullptr, eConv = nullptr, eProj = nullptr;
    static bool init_done = false;
    if (!init_done) {
        cudaFuncSetAttribute(hmma_gemm_kernel<false>,
                             cudaFuncAttributeMaxDynamicSharedMemorySize, GEMM_SMEM);
        cudaFuncSetAttribute(hmma_gemm_kernel<true>,
                             cudaFuncAttributeMaxDynamicSharedMemorySize, GEMM_SMEM);
        cudaStreamCreateWithFlags(&s1, cudaStreamNonBlocking);
        cudaEventCreateWithFlags(&eFork, cudaEventDisableTiming);
        cudaEventCreateWithFlags(&ePrep, cudaEventDisableTiming);
        cudaEventCreateWithFlags(&eConv, cudaEventDisableTiming);
        cudaEventCreateWithFlags(&eProj, cudaEventDisableTiming);
        init_done = true;
    }

    const dim3 tblk(32, 32);
    const dim3 tgrid(2, 4, BB * HH);
    const dim3 ggrid(NPOS / 128, 2);

    // ---- fork side stream ----
    cudaEventRecord(eFork, 0);
    cudaStreamWaitEvent(s1, eFork, 0);

    // s1: weight prep
    prep_weights_kernel<<<CC, CC, 0, s1>>>(in_proj_w, out_w, off_w, mask_w, off_b, mask_b,
                                           w1T, w3T, w2P, b2);
    cudaEventRecord(ePrep, s1);

    // s0: pack + conv
    pack_x_kernel<<<tgrid, tblk>>>(x, xt);
    hmma_gemm_kernel<false><<<ggrid, 256, GEMM_SMEM>>>(xt, conv_w, conv_b, y);
    cudaEventRecord(eConv, 0);

    // s1: in_proj (parallel with dw branch)
    cudaStreamWaitEvent(s1, eConv, 0);
    hmma_gemm_kernel<false><<<ggrid, 256, GEMM_SMEM, s1>>>(y, w1T, in_proj_b, xproj);
    cudaEventRecord(eProj, s1);

    // s0: dw+LN+GELU -> off_mask GEMM
    dw_ln_gelu_kernel<<<NPOS / 8, 256>>>(y, dw_w, dw_b, ln_g, ln_b, dg);
    cudaStreamWaitEvent(0, ePrep, 0);
    hmma_gemm_kernel<false><<<ggrid, 256, GEMM_SMEM>>>(dg, w2P, b2, omp);

    // join: sampler needs xproj (s1) + omp (s0)
    cudaStreamWaitEvent(0, eProj, 0);
    sampler_kernel<<<NPOS / 4, 128>>>(xproj, omp, samp);

    // out_proj writes NCHW directly
    hmma_gemm_kernel<true><<<ggrid, 256, GEMM_SMEM>>>(samp, w3T, out_b, out);
}